// round 16
// baseline (speedup 1.0000x reference)
#include <cuda_runtime.h>
#include <cuda_bf16.h>
#include <cuda_fp16.h>
#include <math_constants.h>
#include <cstdint>

// Problem constants
#define B_   4
#define T_   256
#define U_   64
#define DK_  512      // D_ENC == D_DEC
#define F_   1024     // IN_F
#define V_   1024
#define ROWS_ (B_*T_*U_)   // 65536
#define MPROJ 1280         // 1024 pe rows + 256 pd rows

// Scratch (static __device__ arrays: the sanctioned no-alloc workaround)
__device__ float g_proj[(size_t)MPROJ * F_];              // 5 MB
__device__ __nv_bfloat16 g_xbf[(size_t)MPROJ * DK_];      // 1.25 MB
__device__ __nv_bfloat16 g_WTe[(size_t)F_ * DK_];         // 1 MB
__device__ __nv_bfloat16 g_WTd[(size_t)F_ * DK_];         // 1 MB
__device__ __nv_bfloat16 g_A[(size_t)ROWS_ * F_];         // 128 MB
__device__ __nv_bfloat16 g_WT[(size_t)V_ * F_];           // 2 MB
__device__ __half g_logits[(size_t)ROWS_ * V_];           // 128 MB
__device__ int g_done[512];                               // per packed-rowblock N-tile counters
__device__ int g_tile_ctr;                                // GEMM tile work queue

__device__ __forceinline__ uint32_t smem_u32(const void* p) {
    uint32_t a;
    asm("{ .reg .u64 t; cvta.to.shared.u64 t, %1; cvt.u32.u64 %0, t; }" : "=r"(a) : "l"(p));
    return a;
}

__device__ __forceinline__ float ftanh(float x) {
    x = fmaxf(-4.5f, fminf(4.5f, x));
    const float x2 = x * x;
    float n = x2 + 378.0f;
    n = fmaf(n, x2, 17325.0f);
    n = fmaf(n, x2, 135135.0f);
    n = n * x;
    float q = fmaf(x2, 28.0f, 3150.0f);
    q = fmaf(q, x2, 62370.0f);
    q = fmaf(q, x2, 135135.0f);
    float r = __int_as_float(0x7EF311C3 - __float_as_int(q));
    r = r * fmaf(-q, r, 2.0f);
    r = r * fmaf(-q, r, 2.0f);
    return n * r;
}

__device__ __forceinline__ uint32_t pack_bf16x2(float lo, float hi) {
    uint32_t r;
    asm("cvt.rn.bf16x2.f32 %0, %1, %2;" : "=r"(r) : "f"(hi), "f"(lo));
    return r;
}

// ---------------------------------------------------------------------------
// reset_flags: zero g_done + tile counter before each run (graph replay safe)
// ---------------------------------------------------------------------------
__global__ void reset_flags()
{
    const int i = blockIdx.x * 256 + threadIdx.x;
    if (i < 512) g_done[i] = 0;
    if (i == 512) g_tile_ctr = 0;
}

// ---------------------------------------------------------------------------
// prep: W_fc/W_enc/W_dec transposes -> bf16, enc/dec -> bf16 (one launch)
// ---------------------------------------------------------------------------
__global__ void __launch_bounds__(256) prep(
    const float* __restrict__ W_fc, const float* __restrict__ W_enc,
    const float* __restrict__ W_dec, const float* __restrict__ enc,
    const float* __restrict__ dec)
{
    const int bid = blockIdx.x;
    if (bid < 2048) {
        __shared__ float tile[32][33];
        const float* W;  __nv_bfloat16* D;  int bx, by, kdim;
        if (bid < 1024) { W = W_fc;  D = g_WT;  bx = bid & 31;          by = bid >> 5;          kdim = F_;  }
        else if (bid < 1536) { W = W_enc; D = g_WTe; bx = (bid-1024) & 31; by = (bid-1024) >> 5; kdim = DK_; }
        else { W = W_dec; D = g_WTd; bx = (bid-1536) & 31; by = (bid-1536) >> 5; kdim = DK_; }
        const int x0 = bx * 32;
        const int y0 = by * 32;
        const int tx = threadIdx.x & 31;
        const int ty = threadIdx.x >> 5;
        #pragma unroll
        for (int i = 0; i < 32; i += 8)
            tile[ty + i][tx] = W[(size_t)(y0 + ty + i) * F_ + x0 + tx];
        __syncthreads();
        #pragma unroll
        for (int i = 0; i < 32; i += 8)
            D[(size_t)(x0 + ty + i) * kdim + y0 + tx] = __float2bfloat16(tile[tx][ty + i]);
    } else {
        const int cid = bid - 2048;
        const size_t base = (size_t)cid * 2048 + threadIdx.x * 8;
        const float* src = (base < (size_t)1024 * DK_) ? (enc + base)
                                                       : (dec + (base - (size_t)1024 * DK_));
        float4 a = *(const float4*)src;
        float4 b = *(const float4*)(src + 4);
        uint4 o;
        o.x = pack_bf16x2(a.x, a.y);  o.y = pack_bf16x2(a.z, a.w);
        o.z = pack_bf16x2(b.x, b.y);  o.w = pack_bf16x2(b.z, b.w);
        *(uint4*)(g_xbf + base) = o;
    }
}

// ---------------------------------------------------------------------------
// proj_mma (R12, unchanged): g_proj = concat(enc,dec)_bf16 @ {W_enc,W_dec}^T + bias
// ---------------------------------------------------------------------------
#define KCH    64
#define NSTG   3
#define STG_B  32768
#define SMEM_GEMM (NSTG * STG_B)   // 96 KB

__global__ void __launch_bounds__(256, 2) proj_mma(
    const float* __restrict__ b_enc, const float* __restrict__ b_dec)
{
    extern __shared__ char smem[];
    const uint32_t sb = smem_u32(smem);
    const int tid = threadIdx.x;
    const int n0   = blockIdx.x * 128;
    const int row0 = blockIdx.y * 128;
    const bool pe_part = (blockIdx.y < 8);
    const int w  = tid >> 5, l = tid & 31;
    const int wm = w & 1,  wn = w >> 1;

    const __nv_bfloat16* Abase = g_xbf + (size_t)row0 * DK_;
    const __nv_bfloat16* Bbase = (pe_part ? g_WTe : g_WTd) + (size_t)n0 * DK_;
    const float* bias = pe_part ? b_enc : b_dec;

    const int lr = tid >> 3;
    const int lu = tid & 7;
    const int lsw = lu ^ (lr & 7);

    auto load_stage = [&](int s, int k0) {
        const uint32_t as_ = sb + (uint32_t)s * STG_B;
        const uint32_t bs_ = as_ + 16384;
        #pragma unroll
        for (int i = 0; i < 4; i++) {
            const int r = lr + i * 32;
            asm volatile("cp.async.cg.shared.global [%0], [%1], 16;"
                :: "r"(as_ + r * 128 + lsw * 16),
                   "l"(Abase + (size_t)r * DK_ + k0 + lu * 8));
        }
        #pragma unroll
        for (int i = 0; i < 4; i++) {
            const int r = lr + i * 32;
            asm volatile("cp.async.cg.shared.global [%0], [%1], 16;"
                :: "r"(bs_ + r * 128 + lsw * 16),
                   "l"(Bbase + (size_t)r * DK_ + k0 + lu * 8));
        }
        asm volatile("cp.async.commit_group;" ::: "memory");
    };

    const int ar  = l & 15;
    const int akh = l >> 4;
    const int br  = (l & 7) + ((l >> 4) << 3);
    const int bkh = (l >> 3) & 1;

    float d[4][4][4] = {};

    load_stage(0, 0);
    load_stage(1, KCH);

    #define NS_PROJ 8
    for (int s = 0; s < NS_PROJ; s++) {
        if (s < NS_PROJ - 1) asm volatile("cp.async.wait_group 1;" ::: "memory");
        else                 asm volatile("cp.async.wait_group 0;" ::: "memory");
        __syncthreads();

        if (s + 2 < NS_PROJ) load_stage((s + 2) % NSTG, (s + 2) * KCH);

        const uint32_t as_ = sb + (uint32_t)(s % NSTG) * STG_B;
        const uint32_t bs_ = as_ + 16384;

        #pragma unroll
        for (int kk = 0; kk < 4; kk++) {
            uint32_t bfr[2][4];
            #pragma unroll
            for (int j = 0; j < 2; j++) {
                const int n = wn * 32 + j * 16 + br;
                const uint32_t addr = bs_ + n * 128 + (((kk * 2 + bkh) ^ (n & 7)) * 16);
                asm volatile("ldmatrix.sync.aligned.m8n8.x4.shared.b16 {%0,%1,%2,%3}, [%4];"
                    : "=r"(bfr[j][0]), "=r"(bfr[j][1]), "=r"(bfr[j][2]), "=r"(bfr[j][3])
                    : "r"(addr));
            }
            #pragma unroll
            for (int i = 0; i < 4; i++) {
                const int r = wm * 64 + i * 16 + ar;
                const uint32_t addr = as_ + r * 128 + (((kk * 2 + akh) ^ (r & 7)) * 16);
                uint32_t a0, a1, a2, a3;
                asm volatile("ldmatrix.sync.aligned.m8n8.x4.shared.b16 {%0,%1,%2,%3}, [%4];"
                    : "=r"(a0), "=r"(a1), "=r"(a2), "=r"(a3) : "r"(addr));
                #pragma unroll
                for (int j8 = 0; j8 < 4; j8++) {
                    float* dd = d[i][j8];
                    const uint32_t b0 = bfr[j8 >> 1][(j8 & 1) * 2];
                    const uint32_t b1 = bfr[j8 >> 1][(j8 & 1) * 2 + 1];
                    asm volatile(
                        "mma.sync.aligned.m16n8k16.row.col.f32.bf16.bf16.f32 "
                        "{%0,%1,%2,%3}, {%4,%5,%6,%7}, {%8,%9}, {%0,%1,%2,%3};"
                        : "+f"(dd[0]), "+f"(dd[1]), "+f"(dd[2]), "+f"(dd[3])
                        : "r"(a0), "r"(a1), "r"(a2), "r"(a3), "r"(b0), "r"(b1));
                }
            }
        }
    }

    #pragma unroll
    for (int i = 0; i < 4; i++) {
        const int rr = row0 + wm * 64 + i * 16 + (l >> 2);
        #pragma unroll
        for (int j8 = 0; j8 < 4; j8++) {
            const int cc = n0 + wn * 32 + j8 * 8 + 2 * (l & 3);
            const float bx = bias[cc], by = bias[cc + 1];
            *(float2*)(g_proj + (size_t)rr * F_ + cc) =
                make_float2(d[i][j8][0] + bx, d[i][j8][1] + by);
            *(float2*)(g_proj + (size_t)(rr + 8) * F_ + cc) =
                make_float2(d[i][j8][2] + bx, d[i][j8][3] + by);
        }
    }
}

// ---------------------------------------------------------------------------
// A-build with mask skipping (unchanged).
// ---------------------------------------------------------------------------
__global__ void __launch_bounds__(256) build_A(
    const int* __restrict__ enc_lens, const int* __restrict__ dec_lens)
{
    const int bt = blockIdx.x;
    const int b  = bt >> 8;
    const int tt = bt & (T_ - 1);
    if (tt >= enc_lens[b]) return;
    const int ulim = (dec_lens[b] + 1) & ~1;

    __shared__ float pes[F_];
    const float* per = g_proj + (size_t)bt * F_;
    for (int i = threadIdx.x; i < F_ / 4; i += 256)
        ((float4*)pes)[i] = ((const float4*)per)[i];
    __syncthreads();

    const int k8 = (threadIdx.x & 127) * 8;
    const int uo = threadIdx.x >> 7;
    const float* pdb = g_proj + (size_t)(1024 + b * U_) * F_;
    __nv_bfloat16* arow = g_A + (size_t)bt * U_ * F_;

    const float4 p0 = *(const float4*)(pes + k8);
    const float4 p1 = *(const float4*)(pes + k8 + 4);

    for (int us = 0; us < ulim; us += 2) {
        const int u = us + uo;
        const float* pdr = pdb + (size_t)u * F_ + k8;
        float4 q0 = *(const float4*)pdr;
        float4 q1 = *(const float4*)(pdr + 4);
        uint4 o;
        o.x = pack_bf16x2(ftanh(p0.x + q0.x), ftanh(p0.y + q0.y));
        o.y = pack_bf16x2(ftanh(p0.z + q0.z), ftanh(p0.w + q0.w));
        o.z = pack_bf16x2(ftanh(p1.x + q1.x), ftanh(p1.y + q1.y));
        o.w = pack_bf16x2(ftanh(p1.z + q1.z), ftanh(p1.w + q1.w));
        *(uint4*)(arow + (size_t)u * F_ + k8) = o;
    }
}

// ---------------------------------------------------------------------------
// Fused GEMM + softmax, deadlock-free work queue (R14) + ALIGNMENT FIX:
// sbias must be 16B-aligned for the float4 bias loads (R14 trap: the 4-byte
// s_tile pushed sbias to offset 516 -> LDS.128 misaligned).
// ---------------------------------------------------------------------------
__global__ void __launch_bounds__(256, 2) gemm_softmax(
    const int* __restrict__ enc_lens, const int* __restrict__ dec_lens,
    const float* __restrict__ bfc, float* __restrict__ out)
{
    __shared__ __align__(16) float sbias[V_];
    __shared__ int rowmap[128];
    __shared__ int s_tile;

    const int el0 = enc_lens[0], el1 = enc_lens[1], el2 = enc_lens[2], el3 = enc_lens[3];
    const int dl0 = dec_lens[0], dl1 = dec_lens[1], dl2 = dec_lens[2], dl3 = dec_lens[3];
    const int off1 = el0 * dl0;
    const int off2 = off1 + el1 * dl1;
    const int off3 = off2 + el2 * dl2;
    const int off4 = off3 + el3 * dl3;
    const int ntiles = ((off4 + 127) >> 7) * 8;

    const int tid = threadIdx.x;

    extern __shared__ char smem[];
    const uint32_t sb = smem_u32(smem);
    const int w  = tid >> 5, l = tid & 31;
    const int wm = w & 1,  wn = w >> 1;
    const int lr = tid >> 3;
    const int lu = tid & 7;
    const int lsw = lu ^ (lr & 7);
    const int ar  = l & 15;
    const int akh = l >> 4;
    const int br  = (l & 7) + ((l >> 4) << 3);
    const int bkh = (l >> 3) & 1;

    // ---------------- Phase A: GEMM tiles (work queue) ----------------
    for (;;) {
        __syncthreads();   // protects s_tile and rowmap reuse across iterations
        if (tid == 0) s_tile = atomicAdd(&g_tile_ctr, 1);
        __syncthreads();
        const int tile = s_tile;
        if (tile >= ntiles) break;

        const int rb = tile >> 3;          // packed row block
        const int n0 = (tile & 7) * 128;
        const int row0 = rb * 128;

        if (tid < 128) {
            const int pr = row0 + tid;
            int g = -1;
            if (pr < off4) {
                const int b = (pr >= off1) + (pr >= off2) + (pr >= off3);
                const int base = (b == 0) ? 0 : ((b == 1) ? off1 : ((b == 2) ? off2 : off3));
                const int dl = (b == 0) ? dl0 : ((b == 1) ? dl1 : ((b == 2) ? dl2 : dl3));
                const int p = pr - base;
                const int t = p / dl;
                const int u = p - t * dl;
                g = (b << 14) + (t << 6) + u;
            }
            rowmap[tid] = g;
        }
        __syncthreads();

        const __nv_bfloat16* Bbase = g_WT + (size_t)n0 * F_;
        const __nv_bfloat16* aptr[4];
        #pragma unroll
        for (int i = 0; i < 4; i++) {
            int g = rowmap[lr + i * 32];
            if (g < 0) g = 0;
            aptr[i] = g_A + (size_t)g * F_ + lu * 8;
        }

        auto load_stage = [&](int s, int k0) {
            const uint32_t as_ = sb + (uint32_t)s * STG_B;
            const uint32_t bs_ = as_ + 16384;
            #pragma unroll
            for (int i = 0; i < 4; i++) {
                const int r = lr + i * 32;
                asm volatile("cp.async.cg.shared.global [%0], [%1], 16;"
                    :: "r"(as_ + r * 128 + lsw * 16), "l"(aptr[i] + k0));
            }
            #pragma unroll
            for (int i = 0; i < 4; i++) {
                const int r = lr + i * 32;
                asm volatile("cp.async.cg.shared.global [%0], [%1], 16;"
                    :: "r"(bs_ + r * 128 + lsw * 16),
                       "l"(Bbase + (size_t)r * F_ + k0 + lu * 8));
            }
            asm volatile("cp.async.commit_group;" ::: "memory");
        };

        float d[4][4][4] = {};

        load_stage(0, 0);
        load_stage(1, KCH);

        for (int s = 0; s < 16; s++) {
            if (s < 15) asm volatile("cp.async.wait_group 1;" ::: "memory");
            else        asm volatile("cp.async.wait_group 0;" ::: "memory");
            __syncthreads();

            if (s + 2 < 16) load_stage((s + 2) % NSTG, (s + 2) * KCH);

            const uint32_t as_ = sb + (uint32_t)(s % NSTG) * STG_B;
            const uint32_t bs_ = as_ + 16384;

            #pragma unroll
            for (int kk = 0; kk < 4; kk++) {
                uint32_t bfr[2][4];
                #pragma unroll
                for (int j = 0; j < 2; j++) {
                    const int n = wn * 32 + j * 16 + br;
                    const uint32_t addr = bs_ + n * 128 + (((kk * 2 + bkh) ^ (n & 7)) * 16);
                    asm volatile("ldmatrix.sync.aligned.m8n8.x4.shared.b16 {%0,%1,%2,%3}, [%4];"
                        : "=r"(bfr[j][0]), "=r"(bfr[j][1]), "=r"(bfr[j][2]), "=r"(bfr[j][3])
                        : "r"(addr));
                }
                #pragma unroll
                for (int i = 0; i < 4; i++) {
                    const int r = wm * 64 + i * 16 + ar;
                    const uint32_t addr = as_ + r * 128 + (((kk * 2 + akh) ^ (r & 7)) * 16);
                    uint32_t a0, a1, a2, a3;
                    asm volatile("ldmatrix.sync.aligned.m8n8.x4.shared.b16 {%0,%1,%2,%3}, [%4];"
                        : "=r"(a0), "=r"(a1), "=r"(a2), "=r"(a3) : "r"(addr));
                    #pragma unroll
                    for (int j8 = 0; j8 < 4; j8++) {
                        float* dd = d[i][j8];
                        const uint32_t b0 = bfr[j8 >> 1][(j8 & 1) * 2];
                        const uint32_t b1 = bfr[j8 >> 1][(j8 & 1) * 2 + 1];
                        asm volatile(
                            "mma.sync.aligned.m16n8k16.row.col.f32.bf16.bf16.f32 "
                            "{%0,%1,%2,%3}, {%4,%5,%6,%7}, {%8,%9}, {%0,%1,%2,%3};"
                            : "+f"(dd[0]), "+f"(dd[1]), "+f"(dd[2]), "+f"(dd[3])
                            : "r"(a0), "r"(a1), "r"(a2), "r"(a3), "r"(b0), "r"(b1));
                    }
                }
            }
        }

        #pragma unroll
        for (int i = 0; i < 4; i++) {
            const int lr1 = wm * 64 + i * 16 + (l >> 2);
            const int g1 = rowmap[lr1];
            const int g2 = rowmap[lr1 + 8];
            #pragma unroll
            for (int j8 = 0; j8 < 4; j8++) {
                const int cc = n0 + wn * 32 + j8 * 8 + 2 * (l & 3);
                if (g1 >= 0)
                    *(__half2*)(g_logits + (size_t)g1 * V_ + cc) =
                        __floats2half2_rn(d[i][j8][0], d[i][j8][1]);
                if (g2 >= 0)
                    *(__half2*)(g_logits + (size_t)g2 * V_ + cc) =
                        __floats2half2_rn(d[i][j8][2], d[i][j8][3]);
            }
        }

        __syncthreads();   // all warps' logits stores issued
        if (tid == 0) {
            __threadfence();
            atomicAdd(&g_done[rb], 1);
        }
    }

    // ---------------- Phase B: softmax ----------------
    for (int i = tid; i < V_; i += 256) sbias[i] = bfc[i];
    __syncthreads();

    const int warp = tid >> 5;
    const int lane = tid & 31;

    for (int chunk = blockIdx.x; chunk < 512; chunk += gridDim.x) {
        for (int rr = 0; rr < 16; rr++) {
            const int row = chunk * 128 + rr * 8 + warp;
            const int b  = row >> 14;
            const int tt = (row >> 6) & (T_ - 1);
            const int u  = row & (U_ - 1);
            const int el = (b == 0) ? el0 : ((b == 1) ? el1 : ((b == 2) ? el2 : el3));
            const int dl = (b == 0) ? dl0 : ((b == 1) ? dl1 : ((b == 2) ? dl2 : dl3));

            float4* orow = (float4*)(out + (size_t)row * V_);

            if (tt >= el || u >= dl) {
                float4 z = make_float4(0.f, 0.f, 0.f, 0.f);
                #pragma unroll
                for (int j = 0; j < 4; j++) {
                    const int idx = j * 32 + lane;
                    orow[idx*2]   = z;
                    orow[idx*2+1] = z;
                }
                continue;
            }

            // Wait for this row's packed block to finish all 8 N-tiles.
            const int base = (b == 0) ? 0 : ((b == 1) ? off1 : ((b == 2) ? off2 : off3));
            const int pblk = (base + tt * dl + u) >> 7;
            if (lane == 0) {
                while (*(volatile int*)&g_done[pblk] < 8) __nanosleep(64);
            }
            __syncwarp();
            __threadfence();   // order flag read before logits reads

            const uint4* lrow = (const uint4*)(g_logits + (size_t)row * V_);

            float v[32];
            float mx = -CUDART_INF_F;
            #pragma unroll
            for (int j = 0; j < 4; j++) {
                const int idx = j * 32 + lane;
                uint4 x = lrow[idx];
                const float4 bb0 = ((const float4*)sbias)[idx*2];
                const float4 bb1 = ((const float4*)sbias)[idx*2+1];
                float2 f0 = __half22float2(*(__half2*)&x.x);
                float2 f1 = __half22float2(*(__half2*)&x.y);
                float2 f2 = __half22float2(*(__half2*)&x.z);
                float2 f3 = __half22float2(*(__half2*)&x.w);
                float* vv = v + j * 8;
                vv[0] = f0.x + bb0.x; vv[1] = f0.y + bb0.y;
                vv[2] = f1.x + bb0.z; vv[3] = f1.y + bb0.w;
                vv[4] = f2.x + bb1.x; vv[5] = f2.y + bb1.y;
                vv[6] = f3.x + bb1.z; vv[7] = f3.y + bb1.w;
                #pragma unroll
                for (int e = 0; e < 8; e++) mx = fmaxf(mx, vv[e]);
            }
            #pragma unroll
            for (int o = 16; o > 0; o >>= 1)
                mx = fmaxf(mx, __shfl_xor_sync(0xFFFFFFFFu, mx, o));

            float s = 0.f;
            #pragma unroll
            for (int i = 0; i < 32; i++) s += __expf(v[i] - mx);
            #pragma unroll
            for (int o = 16; o > 0; o >>= 1)
                s += __shfl_xor_sync(0xFFFFFFFFu, s, o);

            const float lse = mx + logf(s);

            #pragma unroll
            for (int j = 0; j < 4; j++) {
                const int idx = j * 32 + lane;
                const float* vv = v + j * 8;
                orow[idx*2]   = make_float4(vv[0]-lse, vv[1]-lse, vv[2]-lse, vv[3]-lse);
                orow[idx*2+1] = make_float4(vv[4]-lse, vv[5]-lse, vv[6]-lse, vv[7]-lse);
            }
        }
    }
}

// ---------------------------------------------------------------------------
extern "C" void kernel_launch(void* const* d_in, const int* in_sizes, int n_in,
                              void* d_out, int out_size)
{
    const float* enc      = (const float*)d_in[0];
    const float* dec      = (const float*)d_in[1];
    const float* W_enc    = (const float*)d_in[2];
    const float* b_enc    = (const float*)d_in[3];
    const float* W_dec    = (const float*)d_in[4];
    const float* b_dec    = (const float*)d_in[5];
    const float* W_fc     = (const float*)d_in[6];
    const float* b_fc     = (const float*)d_in[7];
    const int*   enc_lens = (const int*)d_in[8];
    const int*   dec_lens = (const int*)d_in[9];
    float* out = (float*)d_out;
    (void)in_sizes; (void)n_in; (void)out_size;

    cudaFuncSetAttribute(proj_mma,
                         cudaFuncAttributeMaxDynamicSharedMemorySize, SMEM_GEMM);
    cudaFuncSetAttribute(gemm_softmax,
                         cudaFuncAttributeMaxDynamicSharedMemorySize, SMEM_GEMM);

    // zero completion flags + work queue (each graph replay)
    reset_flags<<<3, 256>>>();
    // Stage inputs: weight transposes + enc/dec bf16 convert
    prep<<<2368, 256>>>(W_fc, W_enc, W_dec, enc, dec);
    // g_proj = concat(enc,dec)_bf16 @ {W_enc,W_dec}^T + bias
    proj_mma<<<dim3(F_/128, MPROJ/128), 256, SMEM_GEMM>>>(b_enc, b_dec);
    // A = bf16(tanh(pe (+) pd))  — dead rows skipped
    build_A<<<B_*T_, 256>>>(enc_lens, dec_lens);
    // Fused GEMM (packed live rows, work-queue) + log-softmax + masking
    gemm_softmax<<<296, 256, SMEM_GEMM>>>(enc_lens, dec_lens, b_fc, out);
}

// round 17
// speedup vs baseline: 1.2568x; 1.2568x over previous
#include <cuda_runtime.h>
#include <cuda_bf16.h>
#include <cuda_fp16.h>
#include <math_constants.h>
#include <cstdint>

// Problem constants
#define B_   4
#define T_   256
#define U_   64
#define DK_  512      // D_ENC == D_DEC
#define F_   1024     // IN_F
#define V_   1024
#define ROWS_ (B_*T_*U_)   // 65536
#define MPROJ 1280         // 1024 pe rows + 256 pd rows

// Scratch (static __device__ arrays: the sanctioned no-alloc workaround)
__device__ float g_proj[(size_t)MPROJ * F_];              // 5 MB
__device__ __nv_bfloat16 g_xbf[(size_t)MPROJ * DK_];      // 1.25 MB
__device__ __nv_bfloat16 g_WTe[(size_t)F_ * DK_];         // 1 MB
__device__ __nv_bfloat16 g_WTd[(size_t)F_ * DK_];         // 1 MB
__device__ __nv_bfloat16 g_A[(size_t)ROWS_ * F_];         // 128 MB
__device__ __nv_bfloat16 g_WT[(size_t)V_ * F_];           // 2 MB
__device__ __half g_logits[(size_t)ROWS_ * V_];           // 128 MB

__device__ __forceinline__ uint32_t smem_u32(const void* p) {
    uint32_t a;
    asm("{ .reg .u64 t; cvta.to.shared.u64 t, %1; cvt.u32.u64 %0, t; }" : "=r"(a) : "l"(p));
    return a;
}

__device__ __forceinline__ float ftanh(float x) {
    x = fmaxf(-4.5f, fminf(4.5f, x));
    const float x2 = x * x;
    float n = x2 + 378.0f;
    n = fmaf(n, x2, 17325.0f);
    n = fmaf(n, x2, 135135.0f);
    n = n * x;
    float q = fmaf(x2, 28.0f, 3150.0f);
    q = fmaf(q, x2, 62370.0f);
    q = fmaf(q, x2, 135135.0f);
    float r = __int_as_float(0x7EF311C3 - __float_as_int(q));
    r = r * fmaf(-q, r, 2.0f);
    r = r * fmaf(-q, r, 2.0f);
    return n * r;
}

__device__ __forceinline__ uint32_t pack_bf16x2(float lo, float hi) {
    uint32_t r;
    asm("cvt.rn.bf16x2.f32 %0, %1, %2;" : "=r"(r) : "f"(hi), "f"(lo));
    return r;
}

// ---------------------------------------------------------------------------
// prep: W_fc/W_enc/W_dec transposes -> bf16, enc/dec -> bf16 (one launch)
// ---------------------------------------------------------------------------
__global__ void __launch_bounds__(256) prep(
    const float* __restrict__ W_fc, const float* __restrict__ W_enc,
    const float* __restrict__ W_dec, const float* __restrict__ enc,
    const float* __restrict__ dec)
{
    const int bid = blockIdx.x;
    if (bid < 2048) {
        __shared__ float tile[32][33];
        const float* W;  __nv_bfloat16* D;  int bx, by, kdim;
        if (bid < 1024) { W = W_fc;  D = g_WT;  bx = bid & 31;          by = bid >> 5;          kdim = F_;  }
        else if (bid < 1536) { W = W_enc; D = g_WTe; bx = (bid-1024) & 31; by = (bid-1024) >> 5; kdim = DK_; }
        else { W = W_dec; D = g_WTd; bx = (bid-1536) & 31; by = (bid-1536) >> 5; kdim = DK_; }
        const int x0 = bx * 32;
        const int y0 = by * 32;
        const int tx = threadIdx.x & 31;
        const int ty = threadIdx.x >> 5;
        #pragma unroll
        for (int i = 0; i < 32; i += 8)
            tile[ty + i][tx] = W[(size_t)(y0 + ty + i) * F_ + x0 + tx];
        __syncthreads();
        #pragma unroll
        for (int i = 0; i < 32; i += 8)
            D[(size_t)(x0 + ty + i) * kdim + y0 + tx] = __float2bfloat16(tile[tx][ty + i]);
    } else {
        const int cid = bid - 2048;
        const size_t base = (size_t)cid * 2048 + threadIdx.x * 8;
        const float* src = (base < (size_t)1024 * DK_) ? (enc + base)
                                                       : (dec + (base - (size_t)1024 * DK_));
        float4 a = *(const float4*)src;
        float4 b = *(const float4*)(src + 4);
        uint4 o;
        o.x = pack_bf16x2(a.x, a.y);  o.y = pack_bf16x2(a.z, a.w);
        o.z = pack_bf16x2(b.x, b.y);  o.w = pack_bf16x2(b.z, b.w);
        *(uint4*)(g_xbf + base) = o;
    }
}

// ---------------------------------------------------------------------------
// proj_mma: g_proj = concat(enc,dec)_bf16 @ {W_enc,W_dec}^T + bias
// ---------------------------------------------------------------------------
#define KCH    64
#define NSTG   3
#define STG_B  32768
#define SMEM_GEMM (NSTG * STG_B)   // 96 KB

__global__ void __launch_bounds__(256, 2) proj_mma(
    const float* __restrict__ b_enc, const float* __restrict__ b_dec)
{
    extern __shared__ char smem[];
    const uint32_t sb = smem_u32(smem);
    const int tid = threadIdx.x;
    const int n0   = blockIdx.x * 128;
    const int row0 = blockIdx.y * 128;
    const bool pe_part = (blockIdx.y < 8);
    const int w  = tid >> 5, l = tid & 31;
    const int wm = w & 1,  wn = w >> 1;

    const __nv_bfloat16* Abase = g_xbf + (size_t)row0 * DK_;
    const __nv_bfloat16* Bbase = (pe_part ? g_WTe : g_WTd) + (size_t)n0 * DK_;
    const float* bias = pe_part ? b_enc : b_dec;

    const int lr = tid >> 3;
    const int lu = tid & 7;
    const int lsw = lu ^ (lr & 7);

    auto load_stage = [&](int s, int k0) {
        const uint32_t as_ = sb + (uint32_t)s * STG_B;
        const uint32_t bs_ = as_ + 16384;
        #pragma unroll
        for (int i = 0; i < 4; i++) {
            const int r = lr + i * 32;
            asm volatile("cp.async.cg.shared.global [%0], [%1], 16;"
                :: "r"(as_ + r * 128 + lsw * 16),
                   "l"(Abase + (size_t)r * DK_ + k0 + lu * 8));
        }
        #pragma unroll
        for (int i = 0; i < 4; i++) {
            const int r = lr + i * 32;
            asm volatile("cp.async.cg.shared.global [%0], [%1], 16;"
                :: "r"(bs_ + r * 128 + lsw * 16),
                   "l"(Bbase + (size_t)r * DK_ + k0 + lu * 8));
        }
        asm volatile("cp.async.commit_group;" ::: "memory");
    };

    const int ar  = l & 15;
    const int akh = l >> 4;
    const int br  = (l & 7) + ((l >> 4) << 3);
    const int bkh = (l >> 3) & 1;

    float d[4][4][4] = {};

    load_stage(0, 0);
    load_stage(1, KCH);

    #define NS_PROJ 8
    for (int s = 0; s < NS_PROJ; s++) {
        if (s < NS_PROJ - 1) asm volatile("cp.async.wait_group 1;" ::: "memory");
        else                 asm volatile("cp.async.wait_group 0;" ::: "memory");
        __syncthreads();

        if (s + 2 < NS_PROJ) load_stage((s + 2) % NSTG, (s + 2) * KCH);

        const uint32_t as_ = sb + (uint32_t)(s % NSTG) * STG_B;
        const uint32_t bs_ = as_ + 16384;

        #pragma unroll
        for (int kk = 0; kk < 4; kk++) {
            uint32_t bfr[2][4];
            #pragma unroll
            for (int j = 0; j < 2; j++) {
                const int n = wn * 32 + j * 16 + br;
                const uint32_t addr = bs_ + n * 128 + (((kk * 2 + bkh) ^ (n & 7)) * 16);
                asm volatile("ldmatrix.sync.aligned.m8n8.x4.shared.b16 {%0,%1,%2,%3}, [%4];"
                    : "=r"(bfr[j][0]), "=r"(bfr[j][1]), "=r"(bfr[j][2]), "=r"(bfr[j][3])
                    : "r"(addr));
            }
            #pragma unroll
            for (int i = 0; i < 4; i++) {
                const int r = wm * 64 + i * 16 + ar;
                const uint32_t addr = as_ + r * 128 + (((kk * 2 + akh) ^ (r & 7)) * 16);
                uint32_t a0, a1, a2, a3;
                asm volatile("ldmatrix.sync.aligned.m8n8.x4.shared.b16 {%0,%1,%2,%3}, [%4];"
                    : "=r"(a0), "=r"(a1), "=r"(a2), "=r"(a3) : "r"(addr));
                #pragma unroll
                for (int j8 = 0; j8 < 4; j8++) {
                    float* dd = d[i][j8];
                    const uint32_t b0 = bfr[j8 >> 1][(j8 & 1) * 2];
                    const uint32_t b1 = bfr[j8 >> 1][(j8 & 1) * 2 + 1];
                    asm volatile(
                        "mma.sync.aligned.m16n8k16.row.col.f32.bf16.bf16.f32 "
                        "{%0,%1,%2,%3}, {%4,%5,%6,%7}, {%8,%9}, {%0,%1,%2,%3};"
                        : "+f"(dd[0]), "+f"(dd[1]), "+f"(dd[2]), "+f"(dd[3])
                        : "r"(a0), "r"(a1), "r"(a2), "r"(a3), "r"(b0), "r"(b1));
                }
            }
        }
    }

    #pragma unroll
    for (int i = 0; i < 4; i++) {
        const int rr = row0 + wm * 64 + i * 16 + (l >> 2);
        #pragma unroll
        for (int j8 = 0; j8 < 4; j8++) {
            const int cc = n0 + wn * 32 + j8 * 8 + 2 * (l & 3);
            const float bx = bias[cc], by = bias[cc + 1];
            *(float2*)(g_proj + (size_t)rr * F_ + cc) =
                make_float2(d[i][j8][0] + bx, d[i][j8][1] + by);
            *(float2*)(g_proj + (size_t)(rr + 8) * F_ + cc) =
                make_float2(d[i][j8][2] + bx, d[i][j8][3] + by);
        }
    }
}

// ---------------------------------------------------------------------------
// A-build with mask skipping (dead rows never read downstream).
// ---------------------------------------------------------------------------
__global__ void __launch_bounds__(256) build_A(
    const int* __restrict__ enc_lens, const int* __restrict__ dec_lens)
{
    const int bt = blockIdx.x;
    const int b  = bt >> 8;
    const int tt = bt & (T_ - 1);
    if (tt >= enc_lens[b]) return;
    const int ulim = (dec_lens[b] + 1) & ~1;

    __shared__ float pes[F_];
    const float* per = g_proj + (size_t)bt * F_;
    for (int i = threadIdx.x; i < F_ / 4; i += 256)
        ((float4*)pes)[i] = ((const float4*)per)[i];
    __syncthreads();

    const int k8 = (threadIdx.x & 127) * 8;
    const int uo = threadIdx.x >> 7;
    const float* pdb = g_proj + (size_t)(1024 + b * U_) * F_;
    __nv_bfloat16* arow = g_A + (size_t)bt * U_ * F_;

    const float4 p0 = *(const float4*)(pes + k8);
    const float4 p1 = *(const float4*)(pes + k8 + 4);

    for (int us = 0; us < ulim; us += 2) {
        const int u = us + uo;
        const float* pdr = pdb + (size_t)u * F_ + k8;
        float4 q0 = *(const float4*)pdr;
        float4 q1 = *(const float4*)(pdr + 4);
        uint4 o;
        o.x = pack_bf16x2(ftanh(p0.x + q0.x), ftanh(p0.y + q0.y));
        o.y = pack_bf16x2(ftanh(p0.z + q0.z), ftanh(p0.w + q0.w));
        o.z = pack_bf16x2(ftanh(p1.x + q1.x), ftanh(p1.y + q1.y));
        o.w = pack_bf16x2(ftanh(p1.z + q1.z), ftanh(p1.w + q1.w));
        *(uint4*)(arow + (size_t)u * F_ + k8) = o;
    }
}

// ---------------------------------------------------------------------------
// Main GEMM via mma.sync with PACKED live rows (R11/R12 proven: 223us,
// tensor 67%): CTA 128x128, warp 64x32, 2 CTA/SM, 3-stage cp.async,
// row map gathers A and scatters fp16 logits.
// ---------------------------------------------------------------------------
__global__ void __launch_bounds__(256, 2) joint_gemm_mma(
    const int* __restrict__ enc_lens, const int* __restrict__ dec_lens)
{
    __shared__ int rowmap[128];

    int off1, off2, off3, off4;
    {
        const int c0 = enc_lens[0] * dec_lens[0];
        const int c1 = enc_lens[1] * dec_lens[1];
        const int c2 = enc_lens[2] * dec_lens[2];
        const int c3 = enc_lens[3] * dec_lens[3];
        off1 = c0; off2 = off1 + c1; off3 = off2 + c2; off4 = off3 + c3;
    }
    const int row0 = blockIdx.y * 128;
    if (row0 >= off4) return;

    const int tid = threadIdx.x;

    if (tid < 128) {
        const int pr = row0 + tid;
        int g = -1;
        if (pr < off4) {
            const int b = (pr >= off1) + (pr >= off2) + (pr >= off3);
            const int base = (b == 0) ? 0 : ((b == 1) ? off1 : ((b == 2) ? off2 : off3));
            const int dl = dec_lens[b];
            const int p = pr - base;
            const int t = p / dl;
            const int u = p - t * dl;
            g = (b << 14) + (t << 6) + u;
        }
        rowmap[tid] = g;
    }
    __syncthreads();

    extern __shared__ char smem[];
    const uint32_t sb = smem_u32(smem);
    const int n0  = blockIdx.x * 128;
    const int w  = tid >> 5, l = tid & 31;
    const int wm = w & 1,  wn = w >> 1;

    const __nv_bfloat16* Bbase = g_WT + (size_t)n0 * F_;

    const int lr = tid >> 3;
    const int lu = tid & 7;
    const int lsw = lu ^ (lr & 7);

    const __nv_bfloat16* aptr[4];
    #pragma unroll
    for (int i = 0; i < 4; i++) {
        int g = rowmap[lr + i * 32];
        if (g < 0) g = 0;
        aptr[i] = g_A + (size_t)g * F_ + lu * 8;
    }

    auto load_stage = [&](int s, int k0) {
        const uint32_t as_ = sb + (uint32_t)s * STG_B;
        const uint32_t bs_ = as_ + 16384;
        #pragma unroll
        for (int i = 0; i < 4; i++) {
            const int r = lr + i * 32;
            asm volatile("cp.async.cg.shared.global [%0], [%1], 16;"
                :: "r"(as_ + r * 128 + lsw * 16), "l"(aptr[i] + k0));
        }
        #pragma unroll
        for (int i = 0; i < 4; i++) {
            const int r = lr + i * 32;
            asm volatile("cp.async.cg.shared.global [%0], [%1], 16;"
                :: "r"(bs_ + r * 128 + lsw * 16),
                   "l"(Bbase + (size_t)r * F_ + k0 + lu * 8));
        }
        asm volatile("cp.async.commit_group;" ::: "memory");
    };

    const int ar  = l & 15;
    const int akh = l >> 4;
    const int br  = (l & 7) + ((l >> 4) << 3);
    const int bkh = (l >> 3) & 1;

    float d[4][4][4] = {};

    load_stage(0, 0);
    load_stage(1, KCH);

    for (int s = 0; s < 16; s++) {
        if (s < 15) asm volatile("cp.async.wait_group 1;" ::: "memory");
        else        asm volatile("cp.async.wait_group 0;" ::: "memory");
        __syncthreads();

        if (s + 2 < 16) load_stage((s + 2) % NSTG, (s + 2) * KCH);

        const uint32_t as_ = sb + (uint32_t)(s % NSTG) * STG_B;
        const uint32_t bs_ = as_ + 16384;

        #pragma unroll
        for (int kk = 0; kk < 4; kk++) {
            uint32_t bfr[2][4];
            #pragma unroll
            for (int j = 0; j < 2; j++) {
                const int n = wn * 32 + j * 16 + br;
                const uint32_t addr = bs_ + n * 128 + (((kk * 2 + bkh) ^ (n & 7)) * 16);
                asm volatile("ldmatrix.sync.aligned.m8n8.x4.shared.b16 {%0,%1,%2,%3}, [%4];"
                    : "=r"(bfr[j][0]), "=r"(bfr[j][1]), "=r"(bfr[j][2]), "=r"(bfr[j][3])
                    : "r"(addr));
            }
            #pragma unroll
            for (int i = 0; i < 4; i++) {
                const int r = wm * 64 + i * 16 + ar;
                const uint32_t addr = as_ + r * 128 + (((kk * 2 + akh) ^ (r & 7)) * 16);
                uint32_t a0, a1, a2, a3;
                asm volatile("ldmatrix.sync.aligned.m8n8.x4.shared.b16 {%0,%1,%2,%3}, [%4];"
                    : "=r"(a0), "=r"(a1), "=r"(a2), "=r"(a3) : "r"(addr));
                #pragma unroll
                for (int j8 = 0; j8 < 4; j8++) {
                    float* dd = d[i][j8];
                    const uint32_t b0 = bfr[j8 >> 1][(j8 & 1) * 2];
                    const uint32_t b1 = bfr[j8 >> 1][(j8 & 1) * 2 + 1];
                    asm volatile(
                        "mma.sync.aligned.m16n8k16.row.col.f32.bf16.bf16.f32 "
                        "{%0,%1,%2,%3}, {%4,%5,%6,%7}, {%8,%9}, {%0,%1,%2,%3};"
                        : "+f"(dd[0]), "+f"(dd[1]), "+f"(dd[2]), "+f"(dd[3])
                        : "r"(a0), "r"(a1), "r"(a2), "r"(a3), "r"(b0), "r"(b1));
                }
            }
        }
    }

    #pragma unroll
    for (int i = 0; i < 4; i++) {
        const int lr1 = wm * 64 + i * 16 + (l >> 2);
        const int g1 = rowmap[lr1];
        const int g2 = rowmap[lr1 + 8];
        #pragma unroll
        for (int j8 = 0; j8 < 4; j8++) {
            const int cc = n0 + wn * 32 + j8 * 8 + 2 * (l & 3);
            if (g1 >= 0)
                *(__half2*)(g_logits + (size_t)g1 * V_ + cc) =
                    __floats2half2_rn(d[i][j8][0], d[i][j8][1]);
            if (g2 >= 0)
                *(__half2*)(g_logits + (size_t)g2 * V_ + cc) =
                    __floats2half2_rn(d[i][j8][2], d[i][j8][3]);
        }
    }
}

// ---------------------------------------------------------------------------
// Bias + log-softmax + mask, fp16 logits input. One warp per row.
// Output stores use .cs streaming hint: out is write-once/never-read, so
// keeping it out of L2 preserves g_logits (128MB ~ L2 size) residency for
// the reads.
// ---------------------------------------------------------------------------
__device__ __forceinline__ void stcs4(float4* p, float4 v) {
    asm volatile("st.global.cs.v4.f32 [%0], {%1, %2, %3, %4};"
                 :: "l"(p), "f"(v.x), "f"(v.y), "f"(v.z), "f"(v.w) : "memory");
}

__global__ void __launch_bounds__(256) softmax_mask_kernel(
    const float* __restrict__ bfc,
    const int* __restrict__ enc_lens, const int* __restrict__ dec_lens,
    float* __restrict__ out)
{
    __shared__ __align__(16) float sbias[V_];
    for (int i = threadIdx.x; i < V_; i += 256) sbias[i] = bfc[i];
    __syncthreads();

    const int warp = threadIdx.x >> 5;
    const int lane = threadIdx.x & 31;
    const int row  = blockIdx.x * 8 + warp;

    const int b  = row >> 14;
    const int tt = (row >> 6) & (T_ - 1);
    const int u  = row & (U_ - 1);

    const uint4*  lrow = (const uint4*)(g_logits + (size_t)row * V_);
    float4*       orow = (float4*)(out + (size_t)row * V_);

    const bool ok = (tt < enc_lens[b]) && (u < dec_lens[b]);
    if (!ok) {
        float4 z = make_float4(0.f, 0.f, 0.f, 0.f);
        #pragma unroll
        for (int j = 0; j < 4; j++) {
            const int idx = j * 32 + lane;
            stcs4(&orow[idx*2],   z);
            stcs4(&orow[idx*2+1], z);
        }
        return;
    }

    float v[32];
    float mx = -CUDART_INF_F;
    #pragma unroll
    for (int j = 0; j < 4; j++) {
        const int idx = j * 32 + lane;
        uint4 x = lrow[idx];
        const float4 bb0 = ((const float4*)sbias)[idx*2];
        const float4 bb1 = ((const float4*)sbias)[idx*2+1];
        float2 f0 = __half22float2(*(__half2*)&x.x);
        float2 f1 = __half22float2(*(__half2*)&x.y);
        float2 f2 = __half22float2(*(__half2*)&x.z);
        float2 f3 = __half22float2(*(__half2*)&x.w);
        float* vv = v + j * 8;
        vv[0] = f0.x + bb0.x; vv[1] = f0.y + bb0.y;
        vv[2] = f1.x + bb0.z; vv[3] = f1.y + bb0.w;
        vv[4] = f2.x + bb1.x; vv[5] = f2.y + bb1.y;
        vv[6] = f3.x + bb1.z; vv[7] = f3.y + bb1.w;
        #pragma unroll
        for (int e = 0; e < 8; e++) mx = fmaxf(mx, vv[e]);
    }
    #pragma unroll
    for (int o = 16; o > 0; o >>= 1)
        mx = fmaxf(mx, __shfl_xor_sync(0xFFFFFFFFu, mx, o));

    float s = 0.f;
    #pragma unroll
    for (int i = 0; i < 32; i++) s += __expf(v[i] - mx);
    #pragma unroll
    for (int o = 16; o > 0; o >>= 1)
        s += __shfl_xor_sync(0xFFFFFFFFu, s, o);

    const float lse = mx + logf(s);

    #pragma unroll
    for (int j = 0; j < 4; j++) {
        const int idx = j * 32 + lane;
        const float* vv = v + j * 8;
        stcs4(&orow[idx*2],
              make_float4(vv[0]-lse, vv[1]-lse, vv[2]-lse, vv[3]-lse));
        stcs4(&orow[idx*2+1],
              make_float4(vv[4]-lse, vv[5]-lse, vv[6]-lse, vv[7]-lse));
    }
}

// ---------------------------------------------------------------------------
extern "C" void kernel_launch(void* const* d_in, const int* in_sizes, int n_in,
                              void* d_out, int out_size)
{
    const float* enc      = (const float*)d_in[0];
    const float* dec      = (const float*)d_in[1];
    const float* W_enc    = (const float*)d_in[2];
    const float* b_enc    = (const float*)d_in[3];
    const float* W_dec    = (const float*)d_in[4];
    const float* b_dec    = (const float*)d_in[5];
    const float* W_fc     = (const float*)d_in[6];
    const float* b_fc     = (const float*)d_in[7];
    const int*   enc_lens = (const int*)d_in[8];
    const int*   dec_lens = (const int*)d_in[9];
    float* out = (float*)d_out;
    (void)in_sizes; (void)n_in; (void)out_size;

    cudaFuncSetAttribute(proj_mma,
                         cudaFuncAttributeMaxDynamicSharedMemorySize, SMEM_GEMM);
    cudaFuncSetAttribute(joint_gemm_mma,
                         cudaFuncAttributeMaxDynamicSharedMemorySize, SMEM_GEMM);

    // Stage inputs: weight transposes + enc/dec bf16 convert
    prep<<<2368, 256>>>(W_fc, W_enc, W_dec, enc, dec);
    // g_proj = concat(enc,dec)_bf16 @ {W_enc,W_dec}^T + bias  (tensor cores)
    proj_mma<<<dim3(F_/128, MPROJ/128), 256, SMEM_GEMM>>>(b_enc, b_dec);
    // A = bf16(tanh(pe (+) pd))  — dead rows skipped
    build_A<<<B_*T_, 256>>>(enc_lens, dec_lens);
    // logits(fp16) = A @ WT^T  — live rows PACKED in M
    joint_gemm_mma<<<dim3(V_/128, ROWS_/128), 256, SMEM_GEMM>>>(enc_lens, dec_lens);
    // out = log_softmax(logits + b_fc) with length masking (.cs output stores)
    softmax_mask_kernel<<<ROWS_/8, 256>>>(b_fc, enc_lens, dec_lens, out);
}